// round 1
// baseline (speedup 1.0000x reference)
#include <cuda_runtime.h>
#include <math.h>

// Problem constants
#define Bn   64
#define Sn   256
#define Dn   300
#define NWn  8192
#define CLn  16
#define CDn  30
#define CHn  30
#define Hn   128
#define Tn   17
#define INW0 330   // D + CH
#define G3   384   // 3*H
#define G6   768   // 2 dirs * 3H

// ---------------- device scratch (static, no allocation) ----------------
__device__ float g_tokenc[(NWn + 1) * CHn];          // padded token encodings
__device__ float g_texts[(size_t)Bn * Sn * INW0];    // [16384][330]
__device__ float g_xg[(size_t)Bn * Sn * G6];         // [16384][768] (reused L0/L1)
__device__ float g_h0[(size_t)Bn * Sn * 256];        // layer0 output
__device__ float g_h1[(size_t)Bn * Sn * 256];        // layer1 output
__device__ float g_mlp[(size_t)Bn * Sn * Hn];        // mlp hidden
__device__ float g_emis[(size_t)Bn * Sn * Tn + 64];  // emissions (+pad)
__device__ float g_llh[Bn];

// ---------------- char CNN ----------------
// grid = NW+1 blocks; block 0 writes the zero row; block w+1 computes word w.
__global__ void char_cnn_kernel(const float* __restrict__ char_emb,
                                const float* __restrict__ conv_w,
                                const float* __restrict__ conv_b,
                                const int* __restrict__ words) {
    __shared__ float s_emb[CLn + 2][CDn];
    __shared__ float s_w[CHn * CDn * 3];
    __shared__ float s_out[CHn * CLn];
    __shared__ int   s_idx[CLn];
    int tid = threadIdx.x;
    int blk = blockIdx.x;
    if (blk == 0) {
        if (tid < CHn) g_tokenc[tid] = 0.f;
        return;
    }
    int w = blk - 1;
    if (tid < CLn) s_idx[tid] = words[w * CLn + tid];
    for (int i = tid; i < CHn * CDn * 3; i += blockDim.x) s_w[i] = conv_w[i];
    if (tid < CDn) { s_emb[0][tid] = 0.f; s_emb[CLn + 1][tid] = 0.f; }
    __syncthreads();
    if (tid < CLn * CDn) {
        int t = tid / CDn, d = tid % CDn;
        s_emb[t + 1][d] = char_emb[s_idx[t] * CDn + d];
    }
    __syncthreads();
    {   // tid in [0,480): one (ch, t) pair
        int ch = tid / CLn, t = tid % CLn;
        float acc = conv_b[ch];
        const float* wr = &s_w[ch * CDn * 3];
#pragma unroll
        for (int d = 0; d < CDn; ++d) {
            acc += s_emb[t][d]     * wr[d * 3 + 0];
            acc += s_emb[t + 1][d] * wr[d * 3 + 1];
            acc += s_emb[t + 2][d] * wr[d * 3 + 2];
        }
        s_out[ch * CLn + t] = fmaxf(acc, 0.f);
    }
    __syncthreads();
    if (tid < CHn) {
        float m = s_out[tid * CLn];
#pragma unroll
        for (int t = 1; t < CLn; ++t) m = fmaxf(m, s_out[tid * CLn + t]);
        g_tokenc[(w + 1) * CHn + tid] = m;
    }
}

// ---------------- build texts: [word_emb | tok_enc] ----------------
__global__ void build_texts_kernel(const float* __restrict__ word_emb,
                                   const int* __restrict__ tokens,
                                   const int* __restrict__ cwi) {
    int m = blockIdx.x;
    int tid = threadIdx.x;
    int tok = tokens[m];
    int ci = cwi[m];
    if (tid < Dn)
        g_texts[(size_t)m * INW0 + tid] = word_emb[(size_t)tok * Dn + tid];
    else if (tid < INW0)
        g_texts[(size_t)m * INW0 + tid] = g_tokenc[ci * CHn + (tid - Dn)];
}

// ---------------- generic SGEMM: C[M][N] = A[M][K] * W^T + bias ----------------
// wNK=1: W is [N][K]; wNK=0: W is [K][N]. Optional relu.
__global__ void gemm_kernel(const float* __restrict__ A,
                            const float* __restrict__ W,
                            const float* __restrict__ bias,
                            float* __restrict__ C,
                            int M, int N, int K, int relu, int wNK) {
    __shared__ float As[16][65];
    __shared__ float Ws[16][65];
    int tid = threadIdx.x;
    int tx = tid % 16, ty = tid / 16;
    int m0 = blockIdx.y * 64, n0 = blockIdx.x * 64;
    float acc[4][4] = {};
    int ktiles = (K + 15) / 16;
    for (int kt = 0; kt < ktiles; ++kt) {
        int k0 = kt * 16;
#pragma unroll
        for (int l = 0; l < 4; ++l) {
            int e = tid + l * 256;
            int kk = e % 16, i = e / 16;
            int m = m0 + i, k = k0 + kk;
            As[kk][i] = (k < K && m < M) ? A[(size_t)m * K + k] : 0.f;
            int n = n0 + i;
            float wv = 0.f;
            if (k < K && n < N)
                wv = wNK ? W[(size_t)n * K + k] : W[(size_t)k * N + n];
            Ws[kk][i] = wv;
        }
        __syncthreads();
#pragma unroll
        for (int kk = 0; kk < 16; ++kk) {
            float a[4], b[4];
#pragma unroll
            for (int i = 0; i < 4; ++i) a[i] = As[kk][ty * 4 + i];
#pragma unroll
            for (int j = 0; j < 4; ++j) b[j] = Ws[kk][tx * 4 + j];
#pragma unroll
            for (int i = 0; i < 4; ++i)
#pragma unroll
                for (int j = 0; j < 4; ++j)
                    acc[i][j] += a[i] * b[j];
        }
        __syncthreads();
    }
#pragma unroll
    for (int i = 0; i < 4; ++i) {
        int m = m0 + ty * 4 + i;
        if (m >= M) continue;
#pragma unroll
        for (int j = 0; j < 4; ++j) {
            int n = n0 + tx * 4 + j;
            if (n >= N) continue;
            float v = acc[i][j] + bias[n];
            if (relu) v = fmaxf(v, 0.f);
            C[(size_t)m * N + n] = v;
        }
    }
}

// ---------------- GRU scan ----------------
// grid = 2*B blocks (dir, batch); 384 threads (one per gate unit).
// W_hh (dir slice) resident in smem, pitch 132 floats -> conflict-free float4.
#define GRU_SMEM (384 * 132 * 4 + 128 * 4 + 384 * 4)

__global__ void gru_kernel(const float* __restrict__ xg,    // [B*S][768]
                           const float* __restrict__ w_hh,  // [2][384][128]
                           const float* __restrict__ b_hh,  // [2][384]
                           const int* __restrict__ lens,
                           float* __restrict__ out) {       // [B*S][256]
    extern __shared__ float sm[];
    float* Wp = sm;                       // [384][132]
    float* sh_h = sm + 384 * 132;         // [128]
    float* sh_hg = sh_h + 128;            // [384]
    int g = threadIdx.x;
    int dir = blockIdx.x / Bn;
    int b = blockIdx.x % Bn;

    const float* Wg = w_hh + (size_t)dir * G3 * Hn;
    for (int i = g; i < G3 * Hn; i += G3) {
        int gg = i >> 7, k = i & 127;
        Wp[gg * 132 + k] = Wg[i];
    }
    if (g < Hn) sh_h[g] = 0.f;
    float bh = b_hh[dir * G3 + g];
    int len = lens[b];
    const float* xgb = xg + (size_t)b * Sn * G6 + dir * G3;
    float* outb = out + (size_t)b * Sn * 256 + dir * Hn;
    __syncthreads();

    const float4* Wp4 = (const float4*)(Wp + g * 132);
    const float4* h4 = (const float4*)sh_h;
    for (int t = 0; t < Sn; ++t) {
        int s = dir ? (Sn - 1 - t) : t;
        float acc0 = 0.f, acc1 = 0.f, acc2 = 0.f, acc3 = 0.f;
#pragma unroll
        for (int k4 = 0; k4 < 32; k4 += 4) {
            float4 w0 = Wp4[k4 + 0], hh0 = h4[k4 + 0];
            float4 w1 = Wp4[k4 + 1], hh1 = h4[k4 + 1];
            float4 w2 = Wp4[k4 + 2], hh2 = h4[k4 + 2];
            float4 w3 = Wp4[k4 + 3], hh3 = h4[k4 + 3];
            acc0 += w0.x * hh0.x + w0.y * hh0.y + w0.z * hh0.z + w0.w * hh0.w;
            acc1 += w1.x * hh1.x + w1.y * hh1.y + w1.z * hh1.z + w1.w * hh1.w;
            acc2 += w2.x * hh2.x + w2.y * hh2.y + w2.z * hh2.z + w2.w * hh2.w;
            acc3 += w3.x * hh3.x + w3.y * hh3.y + w3.z * hh3.z + w3.w * hh3.w;
        }
        sh_hg[g] = bh + ((acc0 + acc1) + (acc2 + acc3));
        __syncthreads();
        if (g < Hn) {
            const float* xs = xgb + (size_t)s * G6;
            float xr = xs[g], xz = xs[Hn + g], xn = xs[2 * Hn + g];
            float hr = sh_hg[g], hz = sh_hg[Hn + g], hn = sh_hg[2 * Hn + g];
            float r = 1.f / (1.f + expf(-(xr + hr)));
            float z = 1.f / (1.f + expf(-(xz + hz)));
            float n = tanhf(xn + r * hn);
            float hp = sh_h[g];
            float hv = (s < len) ? ((1.f - z) * n + z * hp) : hp;
            sh_h[g] = hv;
            outb[(size_t)s * 256 + g] = hv;
        }
        __syncthreads();
    }
}

// ---------------- CRF: score + forward algorithm, one warp per batch ----------------
__global__ void crf_kernel(const float* __restrict__ start,
                           const float* __restrict__ end_,
                           const float* __restrict__ trans,
                           const int* __restrict__ target,
                           const int* __restrict__ lens) {
    int b = blockIdx.x, lane = threadIdx.x;
    const float* E = g_emis + (size_t)b * Sn * Tn;
    const int* tgt = target + b * Sn;
    int len = lens[b];

    // gold score (parallel over s, reduce)
    float partial = 0.f;
    for (int s = 1 + lane; s < Sn; s += 32) {
        if (s < len)
            partial += trans[tgt[s - 1] * Tn + tgt[s]] + E[s * Tn + tgt[s]];
    }
#pragma unroll
    for (int o = 16; o; o >>= 1) partial += __shfl_down_sync(0xffffffffu, partial, o);

    // forward algorithm; lane j < 17 holds alpha_j and trans[:, j]
    float tc[Tn];
    float alpha = -1e30f;
    if (lane < Tn) {
        alpha = start[lane] + E[lane];
#pragma unroll
        for (int i = 0; i < Tn; ++i) tc[i] = trans[i * Tn + lane];
    } else {
#pragma unroll
        for (int i = 0; i < Tn; ++i) tc[i] = 0.f;
    }
    for (int s = 1; s < Sn; ++s) {
        float av[Tn];
        float mx = -1e30f;
#pragma unroll
        for (int i = 0; i < Tn; ++i) {
            av[i] = __shfl_sync(0xffffffffu, alpha, i) + tc[i];
            mx = fmaxf(mx, av[i]);
        }
        float sum = 0.f;
#pragma unroll
        for (int i = 0; i < Tn; ++i) sum += expf(av[i] - mx);
        float e = (lane < Tn) ? E[s * Tn + lane] : 0.f;
        float nw = mx + logf(sum) + e;
        if (lane < Tn && s < len) alpha = nw;
    }
    // log_z
    float v = (lane < Tn) ? alpha + end_[lane] : -1e30f;
    float mx = v;
#pragma unroll
    for (int o = 16; o; o >>= 1) mx = fmaxf(mx, __shfl_xor_sync(0xffffffffu, mx, o));
    float se = expf(v - mx);
#pragma unroll
    for (int o = 16; o; o >>= 1) se += __shfl_xor_sync(0xffffffffu, se, o);
    float logz = mx + logf(se);
    if (lane == 0) {
        float score = partial + start[tgt[0]] + E[tgt[0]] + end_[tgt[len - 1]];
        g_llh[b] = score - logz;
    }
}

__global__ void finalize_kernel(const int* __restrict__ lens, float* __restrict__ out) {
    float sl = 0.f;
    float smk = 0.f;
    for (int b = 0; b < Bn; ++b) { sl += g_llh[b]; smk += (float)lens[b]; }
    out[0] = -sl / smk;
}

// ---------------- launch ----------------
extern "C" void kernel_launch(void* const* d_in, const int* in_sizes, int n_in,
                              void* d_out, int out_size) {
    const float* char_emb  = (const float*)d_in[0];
    const float* conv_w    = (const float*)d_in[1];
    const float* conv_b    = (const float*)d_in[2];
    const float* word_emb  = (const float*)d_in[3];
    const float* w_ih_l0   = (const float*)d_in[4];
    const float* w_hh_l0   = (const float*)d_in[5];
    const float* b_ih_l0   = (const float*)d_in[6];
    const float* b_hh_l0   = (const float*)d_in[7];
    const float* w_ih_l1   = (const float*)d_in[8];
    const float* w_hh_l1   = (const float*)d_in[9];
    const float* b_ih_l1   = (const float*)d_in[10];
    const float* b_hh_l1   = (const float*)d_in[11];
    const float* mlp_w1    = (const float*)d_in[12];
    const float* mlp_b1    = (const float*)d_in[13];
    const float* mlp_w2    = (const float*)d_in[14];
    const float* mlp_b2    = (const float*)d_in[15];
    const float* crf_start = (const float*)d_in[16];
    const float* crf_end   = (const float*)d_in[17];
    const float* crf_trans = (const float*)d_in[18];
    const int* char_words  = (const int*)d_in[19];
    // d_in[20] = batched_char_words_len (unused by the reference forward)
    const int* cwi         = (const int*)d_in[21];
    const int* tokens      = (const int*)d_in[22];
    const int* tokens_len  = (const int*)d_in[23];
    const int* target      = (const int*)d_in[24];
    float* out = (float*)d_out;

    void* pv;
    cudaGetSymbolAddress(&pv, g_texts); float* p_texts = (float*)pv;
    cudaGetSymbolAddress(&pv, g_xg);    float* p_xg    = (float*)pv;
    cudaGetSymbolAddress(&pv, g_h0);    float* p_h0    = (float*)pv;
    cudaGetSymbolAddress(&pv, g_h1);    float* p_h1    = (float*)pv;
    cudaGetSymbolAddress(&pv, g_mlp);   float* p_mlp   = (float*)pv;
    cudaGetSymbolAddress(&pv, g_emis);  float* p_emis  = (float*)pv;

    cudaFuncSetAttribute(gru_kernel, cudaFuncAttributeMaxDynamicSharedMemorySize, GRU_SMEM);

    const int M = Bn * Sn;  // 16384

    // 1) char CNN + zero row
    char_cnn_kernel<<<NWn + 1, 480>>>(char_emb, conv_w, conv_b, char_words);
    // 2) texts gather
    build_texts_kernel<<<M, 352>>>(word_emb, tokens, cwi);
    // 3) layer0 xg = texts @ w_ih_l0^T + b_ih_l0
    gemm_kernel<<<dim3(G6 / 64, M / 64), 256>>>(p_texts, w_ih_l0, b_ih_l0, p_xg,
                                                M, G6, INW0, 0, 1);
    // 4) layer0 scan
    gru_kernel<<<2 * Bn, G3, GRU_SMEM>>>(p_xg, w_hh_l0, b_hh_l0, tokens_len, p_h0);
    // 5) layer1 xg
    gemm_kernel<<<dim3(G6 / 64, M / 64), 256>>>(p_h0, w_ih_l1, b_ih_l1, p_xg,
                                                M, G6, 256, 0, 1);
    // 6) layer1 scan
    gru_kernel<<<2 * Bn, G3, GRU_SMEM>>>(p_xg, w_hh_l1, b_hh_l1, tokens_len, p_h1);
    // 7) MLP hidden (relu)
    gemm_kernel<<<dim3(Hn / 64, M / 64), 256>>>(p_h1, mlp_w1, mlp_b1, p_mlp,
                                                M, Hn, 256, 1, 0);
    // 8) emissions
    gemm_kernel<<<dim3(1, M / 64), 256>>>(p_mlp, mlp_w2, mlp_b2, p_emis,
                                          M, Tn, Hn, 0, 0);
    // 9) CRF per batch
    crf_kernel<<<Bn, 32>>>(crf_start, crf_end, crf_trans, target, tokens_len);
    // 10) reduce to scalar
    finalize_kernel<<<1, 1>>>(tokens_len, out);
}